// round 16
// baseline (speedup 1.0000x reference)
#include <cuda_runtime.h>
#include <cuda_bf16.h>
#include <cuda_fp16.h>
#include <cstdint>

#define TOK   4096      // B*S tokens
#define DMOD  2048      // model dim
#define SEQ   2048      // sequence length
#define NHEAD 16
#define DKH   128       // head dim

// Scratch (device globals: allocation-free per harness rules)
__device__ __half g_X16[3][(size_t)TOK * DMOD]; // q,k,v fp16 inputs
__device__ __half g_Wt4[4][(size_t)DMOD * DMOD];// W^T fp16 [N][K] x {q,k,v,o}
__device__ __half g_Qh[(size_t)TOK * DMOD];     // Q*scale fp16
__device__ __half g_Kh16[(size_t)TOK * DMOD];   // K fp16
__device__ __half g_V16[(size_t)TOK * DMOD];    // V proj fp16 [b,s,d]
__device__ __half g_Vth[(size_t)TOK * DMOD];    // V^T fp16 [b,h,d,s]
__device__ __half g_O16[(size_t)TOK * DMOD];    // attention output fp16

// ---------------------------------------------------------------------------
// helpers
// ---------------------------------------------------------------------------
__device__ __forceinline__ uint32_t smem_to_u32(const void* p) {
    uint32_t a;
    asm("{ .reg .u64 t; cvta.to.shared.u64 t, %1; cvt.u32.u64 %0, t; }"
        : "=r"(a) : "l"(p));
    return a;
}

__device__ __forceinline__ void cp_async16(uint32_t dst, const void* src) {
    asm volatile("cp.async.cg.shared.global [%0], [%1], 16;"
                 :: "r"(dst), "l"(src));
}

__device__ __forceinline__ void ldsm_x4(uint32_t& r0, uint32_t& r1,
                                        uint32_t& r2, uint32_t& r3, uint32_t addr) {
    asm volatile("ldmatrix.sync.aligned.m8n8.x4.shared.b16 {%0,%1,%2,%3}, [%4];"
                 : "=r"(r0), "=r"(r1), "=r"(r2), "=r"(r3) : "r"(addr));
}

__device__ __forceinline__ void mma_f16(float* c,
    uint32_t a0, uint32_t a1, uint32_t a2, uint32_t a3,
    uint32_t b0, uint32_t b1)
{
    asm volatile(
        "mma.sync.aligned.m16n8k16.row.col.f32.f16.f16.f32 "
        "{%0,%1,%2,%3}, {%4,%5,%6,%7}, {%8,%9}, {%0,%1,%2,%3};"
        : "+f"(c[0]), "+f"(c[1]), "+f"(c[2]), "+f"(c[3])
        : "r"(a0), "r"(a1), "r"(a2), "r"(a3), "r"(b0), "r"(b1));
}

// ---------------------------------------------------------------------------
// Batched W transpose+convert: W[K][N] fp32 -> T[N][K] fp16, 4 weights.
// ---------------------------------------------------------------------------
__global__ __launch_bounds__(256)
void wt4_kernel(const float* __restrict__ W0, const float* __restrict__ W1,
                const float* __restrict__ W2, const float* __restrict__ W3,
                __half* __restrict__ T)
{
    __shared__ float ts[32][33];
    const int tx = threadIdx.x & 31;
    const int ty = threadIdx.x >> 5;
    const int n0 = blockIdx.x * 32;
    const int k0 = blockIdx.y * 32;
    const int w  = blockIdx.z;
    const float* W = (w == 0) ? W0 : (w == 1) ? W1 : (w == 2) ? W2 : W3;
    __half* Tw = T + (size_t)w * DMOD * DMOD;

    #pragma unroll
    for (int j = 0; j < 32; j += 8)
        ts[ty + j][tx] = W[(size_t)(k0 + ty + j) * DMOD + n0 + tx];
    __syncthreads();

    #pragma unroll
    for (int j = 0; j < 32; j += 8)
        Tw[(size_t)(n0 + ty + j) * DMOD + k0 + tx] =
            __float2half_rn(ts[tx][ty + j]);
}

// ---------------------------------------------------------------------------
// Batched fp32 -> fp16 elementwise: q,k,v in one launch (blockIdx.y selects)
// ---------------------------------------------------------------------------
__global__ __launch_bounds__(256)
void h16x3_kernel(const float* __restrict__ X0, const float* __restrict__ X1,
                  const float* __restrict__ X2, __half* __restrict__ Y)
{
    const int t = blockIdx.y;
    const float* X = (t == 0) ? X0 : (t == 1) ? X1 : X2;
    __half* Yt = Y + (size_t)t * TOK * DMOD;
    size_t i = ((size_t)blockIdx.x * 256 + threadIdx.x) * 8;
    float4 f0 = *(const float4*)(X + i);
    float4 f1 = *(const float4*)(X + i + 4);
    __half2 h0 = __floats2half2_rn(f0.x, f0.y);
    __half2 h1 = __floats2half2_rn(f0.z, f0.w);
    __half2 h2 = __floats2half2_rn(f1.x, f1.y);
    __half2 h3 = __floats2half2_rn(f1.z, f1.w);
    *(uint4*)(Yt + i) = make_uint4(*(uint32_t*)&h0, *(uint32_t*)&h1,
                                   *(uint32_t*)&h2, *(uint32_t*)&h3);
}

// ---------------------------------------------------------------------------
// V transpose: V16 [b,s,h*128+d] fp16 -> Vth [(b*16+h)*128+d][s] fp16
// ---------------------------------------------------------------------------
__global__ __launch_bounds__(256)
void vtrans_kernel(const __half* __restrict__ Vp, __half* __restrict__ Vh)
{
    __shared__ float ts[32][33];
    const int tx = threadIdx.x & 31;
    const int ty = threadIdx.x >> 5;
    const int bh = blockIdx.z;
    const int b  = bh >> 4, h = bh & 15;
    const int s0 = blockIdx.x * 32;
    const int d0 = blockIdx.y * 32;

    #pragma unroll
    for (int j = 0; j < 32; j += 8)
        ts[ty + j][tx] = __half2float(
            Vp[((size_t)b * SEQ + s0 + ty + j) * DMOD + h * DKH + d0 + tx]);
    __syncthreads();

    #pragma unroll
    for (int j = 0; j < 32; j += 8)
        Vh[((size_t)bh * DKH + d0 + ty + j) * SEQ + s0 + tx] =
            __float2half_rn(ts[tx][ty + j]);
}

// ---------------------------------------------------------------------------
// fp16 mma GEMM, single product: C = A @ W + bias.
// A fp16 [M][K]; B fp16 [N][K]. CTA tile 256x128, BK=64, 4-stage cp.async
// (prefetch issued BEFORE compute each chunk), 512 threads = 16 warps (8Mx2N),
// warp tile 32x64, ldmatrix loads. Accumulation order identical to R13.
// OUT=0: fp32 C.   OUT=1: fp16 of (C+bias)*oscale.
// ---------------------------------------------------------------------------
#define GT_RSB    144                 // 64 halves*2B + 16B pad (144/16=9, odd)
#define GT_ATILE  (256 * GT_RSB)      // 36864
#define GT_BTILE  (128 * GT_RSB)      // 18432
#define GT_STAGE  (GT_ATILE + GT_BTILE)   // 55296
#define GT_NSTG   4
#define GT_SMEM   (GT_NSTG * GT_STAGE)    // 221184
#define GT_KCH    32                  // BK=64 chunks over K=2048

template<int OUT>
__global__ __launch_bounds__(512, 1)
void gemm_mma_kernel(const __half* __restrict__ A,
                     const __half* __restrict__ B,
                     const float* __restrict__ bias,
                     float* __restrict__ C,
                     __half* __restrict__ Yh,
                     float oscale)
{
    extern __shared__ char smem[];
    const uint32_t smemu = smem_to_u32(smem);
    const int tid    = threadIdx.x;
    const int lane   = tid & 31;
    const int wid    = tid >> 5;
    const int warp_m = wid & 7;       // 8 m-warps: rows warp_m*32..+31
    const int warp_n = wid >> 3;      // 2 n-warps: cols warp_n*64..+63
    const int r4     = lane >> 2;
    const int kq     = lane & 3;
    const int li  = lane & 7;
    const int l8  = (lane >> 3) & 1;
    const int l16 = (lane >> 4) & 1;
    const int n0 = blockIdx.x << 7;   // 128-wide n tile
    const int m0 = blockIdx.y << 8;   // 256-wide m tile

    float acc[2][8][4];
    #pragma unroll
    for (int i = 0; i < 2; i++)
        #pragma unroll
        for (int j = 0; j < 8; j++)
            #pragma unroll
            for (int p = 0; p < 4; p++) acc[i][j][p] = 0.f;

    // A: 256 rows x 8 segs = 2048 units; B: 128 x 8 = 1024; 6/thread
    auto issue = [&](int c, int s) {
        const int k0e = c << 6;
        #pragma unroll
        for (int it = 0; it < 6; ++it) {
            int idx = it * 512 + tid;          // 0..3071
            const __half* src;
            uint32_t dst;
            if (idx < 2048) {                  // A tile
                int r  = idx >> 3;
                int cc = idx & 7;
                src = A + (size_t)(m0 + r) * DMOD + k0e + cc * 8;
                dst = smemu + s * GT_STAGE + r * GT_RSB + cc * 16;
            } else {                           // B tile
                int u  = idx - 2048;
                int r  = u >> 3;
                int cc = u & 7;
                src = B + (size_t)(n0 + r) * DMOD + k0e + cc * 8;
                dst = smemu + s * GT_STAGE + GT_ATILE + r * GT_RSB + cc * 16;
            }
            cp_async16(dst, src);
        }
    };

    issue(0, 0);
    asm volatile("cp.async.commit_group;" ::: "memory");
    issue(1, 1);
    asm volatile("cp.async.commit_group;" ::: "memory");
    issue(2, 2);
    asm volatile("cp.async.commit_group;" ::: "memory");

    for (int c = 0; c < GT_KCH; ++c) {
        // chunk c arrived when <=2 groups (c+1, c+2) remain outstanding
        asm volatile("cp.async.wait_group 2;" ::: "memory");
        __syncthreads();

        // prefetch chunk c+3 BEFORE compute so GMEM loads overlap the MMAs.
        // Stage (c+3)%4 != c%4; stage c%4 is only rewritten by issue(c+4),
        // which happens after the next __syncthreads (all reads of c done).
        if (c + 3 < GT_KCH) issue(c + 3, (c + 3) % GT_NSTG);
        asm volatile("cp.async.commit_group;" ::: "memory");

        const uint32_t stg = smemu + (c % GT_NSTG) * GT_STAGE;
        #pragma unroll
        for (int ks = 0; ks < 4; ++ks) {
            const uint32_t kb = ks * 32 + l16 * 16;
            uint32_t a[2][4];
            #pragma unroll
            for (int i = 0; i < 2; ++i) {
                uint32_t aadr = stg + (warp_m * 32 + i * 16 + l8 * 8 + li) * GT_RSB + kb;
                ldsm_x4(a[i][0], a[i][1], a[i][2], a[i][3], aadr);
            }
            #pragma unroll
            for (int j = 0; j < 8; j += 2) {
                // paired x4: matrices for n-tiles j (b0,b1) and j+1 (b2,b3)
                uint32_t badr = stg + GT_ATILE +
                                (warp_n * 64 + j * 8 + l16 * 8 + li) * GT_RSB +
                                ks * 32 + l8 * 16;
                uint32_t b0, b1, b2, b3;
                ldsm_x4(b0, b1, b2, b3, badr);
                #pragma unroll
                for (int i = 0; i < 2; ++i) {
                    mma_f16(acc[i][j],     a[i][0], a[i][1], a[i][2], a[i][3], b0, b1);
                    mma_f16(acc[i][j + 1], a[i][0], a[i][1], a[i][2], a[i][3], b2, b3);
                }
            }
        }
    }

    #pragma unroll
    for (int j = 0; j < 8; ++j) {
        int col = n0 + warp_n * 64 + j * 8 + kq * 2;
        float b0 = bias[col], b1 = bias[col + 1];
        #pragma unroll
        for (int i = 0; i < 2; ++i) {
            int row = m0 + warp_m * 32 + i * 16 + r4;
            float y0 = acc[i][j][0] + b0, y1 = acc[i][j][1] + b1;
            float y2 = acc[i][j][2] + b0, y3 = acc[i][j][3] + b1;
            if (OUT == 0) {
                *(float2*)&C[(size_t)row * DMOD + col]       = make_float2(y0, y1);
                *(float2*)&C[(size_t)(row + 8) * DMOD + col] = make_float2(y2, y3);
            } else {
                __half2 H0 = __floats2half2_rn(y0 * oscale, y1 * oscale);
                __half2 H1 = __floats2half2_rn(y2 * oscale, y3 * oscale);
                *(__half2*)&Yh[(size_t)row * DMOD + col]       = H0;
                *(__half2*)&Yh[(size_t)(row + 8) * DMOD + col] = H1;
            }
        }
    }
}

// ---------------------------------------------------------------------------
// Flash attention (frozen since R10): fp16 mma + ldmatrix.
// CTA: one (b,h), 128 q rows; 8 warps, each owns 16 full rows.
// Single-product QK^T; P fp16; V fp16. Output fp16. K/V double-buffered.
// ---------------------------------------------------------------------------
#define FL_RSQ  272                   // 128 halves*2B + 16B pad
#define FL_RSV  144                   // 64 halves*2B + 16B pad
#define FL_QHS  0                     // Q: 34816
#define FL_K0   34816                 // K double buf: 2*17408
#define FL_V0   69632                 // V double buf: 2*18432
#define FL_SMEM 106496

__global__ __launch_bounds__(256, 1)
void flash_mma_kernel(const __half* __restrict__ Qh,
                      const __half* __restrict__ Kh,
                      const __half* __restrict__ Vh,
                      __half* __restrict__ O16)
{
    extern __shared__ char smem[];
    const uint32_t su = smem_to_u32(smem);
    const int tid  = threadIdx.x;
    const int lane = tid & 31;
    const int wid  = tid >> 5;
    const int r4 = lane >> 2, kq = lane & 3;
    const int li  = lane & 7;
    const int l8  = (lane >> 3) & 1;
    const int l16 = (lane >> 4) & 1;
    const int q0 = blockIdx.x << 7;
    const int h  = blockIdx.y, b = blockIdx.z;
    const size_t qkbase = (size_t)b * SEQ * DMOD + (size_t)h * DKH;
    const size_t vtbase = ((size_t)b * NHEAD + h) * DKH * SEQ;

    auto load_kv = [&](int t, int st) {
        const int n0 = t << 6;
        const uint32_t kd = su + FL_K0 + st * 17408;
        const uint32_t vd = su + FL_V0 + st * 18432;
        #pragma unroll
        for (int u = 0; u < 4; u++) {
            int idx = u * 256 + tid;
            int r = idx >> 4, sg = idx & 15;
            cp_async16(kd + r * FL_RSQ + sg * 16,
                       Kh + qkbase + (size_t)(n0 + r) * DMOD + sg * 8);
        }
        #pragma unroll
        for (int u = 0; u < 4; u++) {
            int idx = u * 256 + tid;
            int r = idx >> 3, sg = idx & 7;
            cp_async16(vd + r * FL_RSV + sg * 16,
                       Vh + vtbase + (size_t)r * SEQ + n0 + sg * 8);
        }
    };

    #pragma unroll
    for (int u = 0; u < 8; u++) {
        int idx = u * 256 + tid;
        int r = idx >> 4, sg = idx & 15;
        cp_async16(su + FL_QHS + r * FL_RSQ + sg * 16,
                   Qh + qkbase + (size_t)(q0 + r) * DMOD + sg * 8);
    }
    asm volatile("cp.async.commit_group;" ::: "memory");
    load_kv(0, 0);
    asm volatile("cp.async.commit_group;" ::: "memory");
    asm volatile("cp.async.wait_group 0;" ::: "memory");
    __syncthreads();

    const uint32_t qrowoff = (wid * 16 + l8 * 8 + li) * FL_RSQ + l16 * 16;
    uint32_t aqh[8][4];
    #pragma unroll
    for (int k = 0; k < 8; k++)
        ldsm_x4(aqh[k][0], aqh[k][1], aqh[k][2], aqh[k][3],
                su + FL_QHS + qrowoff + k * 32);

    float oc[16][4];
    #pragma unroll
    for (int nf = 0; nf < 16; nf++)
        #pragma unroll
        for (int p = 0; p < 4; p++) oc[nf][p] = 0.f;
    float m0 = -1e30f, m1 = -1e30f, l0 = 0.f, l1 = 0.f;

    for (int t = 0; t < 32; t++) {
        const int st = t & 1;
        const uint32_t ks = su + FL_K0 + st * 17408;
        const uint32_t vs = su + FL_V0 + st * 18432;

        if (t + 1 < 32) {
            load_kv(t + 1, st ^ 1);
            asm volatile("cp.async.commit_group;" ::: "memory");
        }

        float sc[8][4];
        #pragma unroll
        for (int nf = 0; nf < 8; nf++)
            #pragma unroll
            for (int p = 0; p < 4; p++) sc[nf][p] = 0.f;

        #pragma unroll
        for (int k = 0; k < 8; k++) {
            #pragma unroll
            for (int nf = 0; nf < 8; nf += 2) {
                uint32_t kadr = ks + (nf * 8 + l16 * 8 + li) * FL_RSQ +
                                l8 * 16 + k * 32;
                uint32_t k0, k1, k2, k3;
                ldsm_x4(k0, k1, k2, k3, kadr);
                mma_f16(sc[nf],     aqh[k][0], aqh[k][1], aqh[k][2], aqh[k][3], k0, k1);
                mma_f16(sc[nf + 1], aqh[k][0], aqh[k][1], aqh[k][2], aqh[k][3], k2, k3);
            }
        }

        float mx0 = -1e30f, mx1 = -1e30f;
        #pragma unroll
        for (int nf = 0; nf < 8; nf++) {
            mx0 = fmaxf(mx0, fmaxf(sc[nf][0], sc[nf][1]));
            mx1 = fmaxf(mx1, fmaxf(sc[nf][2], sc[nf][3]));
        }
        mx0 = fmaxf(mx0, __shfl_xor_sync(0xffffffffu, mx0, 1));
        mx0 = fmaxf(mx0, __shfl_xor_sync(0xffffffffu, mx0, 2));
        mx1 = fmaxf(mx1, __shfl_xor_sync(0xffffffffu, mx1, 1));
        mx1 = fmaxf(mx1, __shfl_xor_sync(0xffffffffu, mx1, 2));

        const float mn0 = fmaxf(m0, mx0), mn1 = fmaxf(m1, mx1);
        const float c0 = __expf(m0 - mn0), c1 = __expf(m1 - mn1);
        float s0 = 0.f, s1 = 0.f;
        uint32_t pa[4][4];
        #pragma unroll
        for (int nf = 0; nf < 8; nf++) {
            float p0 = __expf(sc[nf][0] - mn0);
            float p1 = __expf(sc[nf][1] - mn0);
            float p2 = __expf(sc[nf][2] - mn1);
            float p3 = __expf(sc[nf][3] - mn1);
            s0 += p0 + p1; s1 += p2 + p3;
            __half2 hA = __floats2half2_rn(p0, p1);
            __half2 hB = __floats2half2_rn(p2, p3);
            pa[nf >> 1][(nf & 1) ? 2 : 0] = *(uint32_t*)&hA;
            pa[nf >> 1][(nf & 1) ? 3 : 1] = *(uint32_t*)&hB;
        }
        s0 += __shfl_xor_sync(0xffffffffu, s0, 1);
        s0 += __shfl_xor_sync(0xffffffffu, s0, 2);
        s1 += __shfl_xor_sync(0xffffffffu, s1, 1);
        s1 += __shfl_xor_sync(0xffffffffu, s1, 2);
        l0 = l0 * c0 + s0; m0 = mn0;
        l1 = l1 * c1 + s1; m1 = mn1;
        #pragma unroll
        for (int nf = 0; nf < 16; nf++) {
            oc[nf][0] *= c0; oc[nf][1] *= c0;
            oc[nf][2] *= c1; oc[nf][3] *= c1;
        }

        #pragma unroll
        for (int k = 0; k < 4; k++) {
            #pragma unroll
            for (int nf = 0; nf < 16; nf += 2) {
                uint32_t vadr = vs + (nf * 8 + l16 * 8 + li) * FL_RSV +
                                k * 32 + l8 * 16;
                uint32_t v0, v1, v2, v3;
                ldsm_x4(v0, v1, v2, v3, vadr);
                mma_f16(oc[nf],     pa[k][0], pa[k][1], pa[k][2], pa[k][3], v0, v1);
                mma_f16(oc[nf + 1], pa[k][0], pa[k][1], pa[k][2], pa[k][3], v2, v3);
            }
        }

        if (t + 1 < 32) {
            asm volatile("cp.async.wait_group 0;" ::: "memory");
            __syncthreads();
        }
    }

    const float inv0 = 1.f / l0, inv1 = 1.f / l1;
    #pragma unroll
    for (int nf = 0; nf < 16; nf++) {
        int col  = nf * 8 + kq * 2;
        int row0 = q0 + wid * 16 + r4;
        __half2 H0 = __floats2half2_rn(oc[nf][0] * inv0, oc[nf][1] * inv0);
        __half2 H1 = __floats2half2_rn(oc[nf][2] * inv1, oc[nf][3] * inv1);
        *(__half2*)&O16[qkbase + (size_t)row0 * DMOD + col]       = H0;
        *(__half2*)&O16[qkbase + (size_t)(row0 + 8) * DMOD + col] = H1;
    }
}

// ---------------------------------------------------------------------------
// Launch
// ---------------------------------------------------------------------------
extern "C" void kernel_launch(void* const* d_in, const int* in_sizes, int n_in,
                              void* d_out, int out_size)
{
    const float* q  = (const float*)d_in[0];
    const float* k  = (const float*)d_in[1];
    const float* v  = (const float*)d_in[2];
    const float* Wq = (const float*)d_in[3];
    const float* bq = (const float*)d_in[4];
    const float* Wk = (const float*)d_in[5];
    const float* bk = (const float*)d_in[6];
    const float* Wv = (const float*)d_in[7];
    const float* bv = (const float*)d_in[8];
    const float* Wo = (const float*)d_in[9];
    const float* bo = (const float*)d_in[10];
    float* out = (float*)d_out;

    __half *X16, *Wt4, *Qh, *Kh, *V16, *Vth, *O16;
    cudaGetSymbolAddress((void**)&X16,  g_X16);
    cudaGetSymbolAddress((void**)&Wt4,  g_Wt4);
    cudaGetSymbolAddress((void**)&Qh,   g_Qh);
    cudaGetSymbolAddress((void**)&Kh,   g_Kh16);
    cudaGetSymbolAddress((void**)&V16,  g_V16);
    cudaGetSymbolAddress((void**)&Vth,  g_Vth);
    cudaGetSymbolAddress((void**)&O16,  g_O16);

    const size_t XP = (size_t)TOK * DMOD;       // per-tensor plane
    const size_t WP = (size_t)DMOD * DMOD;

    cudaFuncSetAttribute(gemm_mma_kernel<0>,
                         cudaFuncAttributeMaxDynamicSharedMemorySize, GT_SMEM);
    cudaFuncSetAttribute(gemm_mma_kernel<1>,
                         cudaFuncAttributeMaxDynamicSharedMemorySize, GT_SMEM);
    cudaFuncSetAttribute(flash_mma_kernel,
                         cudaFuncAttributeMaxDynamicSharedMemorySize, FL_SMEM);

    const dim3 gt(DMOD / 32, DMOD / 32, 4);       // batched W transpose
    const dim3 gg(DMOD / 128, TOK / 256);         // gemm grid (16, 16)
    const dim3 gh((TOK * DMOD) / (256 * 8), 3);   // batched h16
    const float scale = 0.08838834764831845f;     // 1/sqrt(128)

    // all conversions upfront (2 launches)
    h16x3_kernel<<<gh, 256>>>(q, k, v, X16);
    wt4_kernel<<<gt, 256>>>(Wq, Wk, Wv, Wo, Wt4);

    // projections back-to-back
    gemm_mma_kernel<1><<<gg, 512, GT_SMEM>>>(X16,          Wt4,          bq,
                                             nullptr, Qh,  scale);
    gemm_mma_kernel<1><<<gg, 512, GT_SMEM>>>(X16 + XP,     Wt4 + WP,     bk,
                                             nullptr, Kh,  1.0f);
    gemm_mma_kernel<1><<<gg, 512, GT_SMEM>>>(X16 + 2 * XP, Wt4 + 2 * WP, bv,
                                             nullptr, V16, 1.0f);
    vtrans_kernel<<<dim3(SEQ / 32, DKH / 32, 2 * NHEAD), 256>>>(V16, Vth);

    // attention -> fp16 directly into final-GEMM A operand
    flash_mma_kernel<<<dim3(SEQ / 128, NHEAD, 2), 256, FL_SMEM>>>(
        Qh, Kh, Vth, O16);

    // output projection (fp32 out)
    gemm_mma_kernel<0><<<gg, 512, GT_SMEM>>>(O16, Wt4 + 3 * WP, bo,
                                             out, nullptr, 1.0f);
}